// round 13
// baseline (speedup 1.0000x reference)
#include <cuda_runtime.h>
#include <cuda_bf16.h>
#include <cstdint>

#define B_SZ  512
#define NIN   1024
#define NMID  8192
#define NOUT  1000
#define MPAD  1024
#define FAN   64
#define NCOND 2

// warp-MMA GEMM tiling (fp32 staged, hi/lo bf16 split at STS) -- R10-proven
#define TBM 128
#define TBN 128
#define TBK 16            // real-K elems per chunk
#define ROWB 48           // bf16 tile row stride bytes (32B data + 16B pad; conflict-free)
#define GEMM_THREADS 256

// ---------------------------------------------------------------------------
// Scratch (static device globals; referenced ONLY inside device code --
// passing them as kernel args from host binds the host shadow, which on
// GB300/ATS silently reads zeros / writes host RAM: the R5/R6 bug)
// ---------------------------------------------------------------------------
__device__ float4 g_act0v[(size_t)NMID * B_SZ / 4];           // fp32 [o][b]
__device__ float4 g_act1v[(size_t)NMID * B_SZ / 4];           // fp32 [o][b]
__device__ float  g_a1t[(size_t)B_SZ * NMID];                 // fp32 [b][o] (cond1 out, GEMM3 B)
__device__ float4 g_wf4[NCOND][(size_t)(FAN / 4) * NMID];     // cond w packed
__device__ uint4  g_if4[(size_t)(FAN / 8) * NMID];            // cond idx packed u16

// ---------------------------------------------------------------------------
__device__ __forceinline__ void mma16816(float* d,
                                         uint32_t a0, uint32_t a1, uint32_t a2, uint32_t a3,
                                         uint32_t b0, uint32_t b1) {
    asm volatile(
        "mma.sync.aligned.m16n8k16.row.col.f32.bf16.bf16.f32 "
        "{%0,%1,%2,%3}, {%4,%5,%6,%7}, {%8,%9}, {%0,%1,%2,%3};"
        : "+f"(d[0]), "+f"(d[1]), "+f"(d[2]), "+f"(d[3])
        : "r"(a0), "r"(a1), "r"(a2), "r"(a3), "r"(b0), "r"(b1));
}

__device__ __forceinline__ void split_bf16(float v, __nv_bfloat16& h, __nv_bfloat16& l) {
    h = __float2bfloat16(v);
    l = __float2bfloat16(v - __bfloat162float(h));
}
// split float4 into packed hi (ushort4) and lo (ushort4)
__device__ __forceinline__ void split4(float4 v, ushort4& hv, ushort4& lv) {
    __nv_bfloat16 h0, h1, h2, h3, l0, l1, l2, l3;
    split_bf16(v.x, h0, l0); split_bf16(v.y, h1, l1);
    split_bf16(v.z, h2, l2); split_bf16(v.w, h3, l3);
    hv = make_ushort4(__bfloat16_as_ushort(h0), __bfloat16_as_ushort(h1),
                      __bfloat16_as_ushort(h2), __bfloat16_as_ushort(h3));
    lv = make_ushort4(__bfloat16_as_ushort(l0), __bfloat16_as_ushort(l1),
                      __bfloat16_as_ushort(l2), __bfloat16_as_ushort(l3));
}

// ---------------------------------------------------------------------------
// cond prep
// ---------------------------------------------------------------------------
__global__ void prep_w_kernel(const float* __restrict__ Wmid) {
    int t = blockIdx.x * blockDim.x + threadIdx.x;
    if (t >= NCOND * (FAN / 4) * NMID) return;
    int phase = t / ((FAN / 4) * NMID);
    int rem = t - phase * (FAN / 4) * NMID;
    int g = rem / NMID, o = rem - g * NMID;
    const float* src = Wmid + (size_t)(phase * NMID + o) * FAN + g * 4;
    g_wf4[phase][(size_t)g * NMID + o] = make_float4(src[0], src[1], src[2], src[3]);
}
__global__ void prep_i_kernel(const int* __restrict__ idx) {
    int t = blockIdx.x * blockDim.x + threadIdx.x;
    if (t >= (FAN / 8) * NMID) return;
    int g = t / NMID, o = t - g * NMID;
    const int* src = idx + (size_t)o * FAN + g * 8;
    uint4 v;
    v.x = (unsigned)(src[0] & (NMID - 1)) | ((unsigned)(src[1] & (NMID - 1)) << 16);
    v.y = (unsigned)(src[2] & (NMID - 1)) | ((unsigned)(src[3] & (NMID - 1)) << 16);
    v.z = (unsigned)(src[4] & (NMID - 1)) | ((unsigned)(src[5] & (NMID - 1)) << 16);
    v.w = (unsigned)(src[6] & (NMID - 1)) | ((unsigned)(src[7] & (NMID - 1)) << 16);
    g_if4[(size_t)g * NMID + o] = v;
}

// ---------------------------------------------------------------------------
// warp-MMA bf16-split GEMM (R10-proven), fp32 inputs converted during staging:
//   D[m][n] = sum_k A[m][k]*B[n][k], evaluated as Ah*Bh + Ah*Bl + Al*Bh
// MODE 0: A=Win(arg) B=x(arg),  Ks=NIN,  out: g_act0[m*B_SZ+n]=relu(D+bias[m])
// MODE 1: A=Wout(arg) B=g_a1t,  Ks=NMID, out: atomicAdd(out[n*NOUT+m], D); A rows >= NOUT -> 0
// ---------------------------------------------------------------------------
template <int MODE>
__global__ __launch_bounds__(GEMM_THREADS) void mma_gemm(
    const float* __restrict__ Asrc, const float* __restrict__ Bsrc,
    const float* __restrict__ bias, float* __restrict__ outp, int kIters)
{
    const float* __restrict__ A = Asrc;
    const float* __restrict__ B = (MODE == 0) ? Bsrc : (const float*)g_a1t;
    float* out = (MODE == 0) ? (float*)g_act0v : outp;
    const int Ks = (MODE == 0) ? NIN : NMID;

    __shared__ __align__(16) char smAh[TBM * ROWB];
    __shared__ __align__(16) char smAl[TBM * ROWB];
    __shared__ __align__(16) char smBh[TBN * ROWB];
    __shared__ __align__(16) char smBl[TBN * ROWB];

    int tid = threadIdx.x;
    int wid = tid >> 5, lid = tid & 31;
    int g = lid >> 2, t = lid & 3;
    int wm = (wid >> 1) * 32;               // warp M offset in tile
    int wn = (wid & 1) * 64;                // warp N offset in tile
    int m0 = blockIdx.y * TBM;
    int n0 = blockIdx.x * TBN;
    int kk0 = blockIdx.z * kIters * TBK;

    // staging: tile = 128 rows x 16 fp32 (64B) = 512 chunks of 16B; 2 per thread
    int ra0 = tid >> 2,          sa0 = (tid & 3) * 4;            // seg in floats
    int ra1 = (tid + 256) >> 2,  sa1 = ((tid + 256) & 3) * 4;

    float4 fA0, fA1, fB0, fB1;
    float acc[2][8][4] = {};

#define LDG_CHUNKS(it)                                                             \
    do {                                                                           \
        int kk = kk0 + (it) * TBK;                                                 \
        fA0 = (MODE == 1 && m0 + ra0 >= NOUT) ? make_float4(0.f, 0.f, 0.f, 0.f)    \
              : __ldg((const float4*)(A + (size_t)(m0 + ra0) * Ks + kk + sa0));    \
        fA1 = (MODE == 1 && m0 + ra1 >= NOUT) ? make_float4(0.f, 0.f, 0.f, 0.f)    \
              : __ldg((const float4*)(A + (size_t)(m0 + ra1) * Ks + kk + sa1));    \
        fB0 = __ldg((const float4*)(B + (size_t)(n0 + ra0) * Ks + kk + sa0));      \
        fB1 = __ldg((const float4*)(B + (size_t)(n0 + ra1) * Ks + kk + sa1));      \
    } while (0)

#define CVT_STS()                                                                  \
    do {                                                                           \
        ushort4 hv, lv;                                                            \
        split4(fA0, hv, lv);                                                       \
        *(ushort4*)(smAh + ra0 * ROWB + sa0 * 2) = hv;                             \
        *(ushort4*)(smAl + ra0 * ROWB + sa0 * 2) = lv;                             \
        split4(fA1, hv, lv);                                                       \
        *(ushort4*)(smAh + ra1 * ROWB + sa1 * 2) = hv;                             \
        *(ushort4*)(smAl + ra1 * ROWB + sa1 * 2) = lv;                             \
        split4(fB0, hv, lv);                                                       \
        *(ushort4*)(smBh + ra0 * ROWB + sa0 * 2) = hv;                             \
        *(ushort4*)(smBl + ra0 * ROWB + sa0 * 2) = lv;                             \
        split4(fB1, hv, lv);                                                       \
        *(ushort4*)(smBh + ra1 * ROWB + sa1 * 2) = hv;                             \
        *(ushort4*)(smBl + ra1 * ROWB + sa1 * 2) = lv;                             \
    } while (0)

    LDG_CHUNKS(0);

    int koff = 4 * t;                       // byte offset in 32B bf16 row
    for (int it = 0; it < kIters; it++) {
        __syncthreads();                    // previous compute done everywhere
        CVT_STS();
        __syncthreads();
        if (it + 1 < kIters) LDG_CHUNKS(it + 1);   // hidden under compute below

        uint32_t a[2][4];
        // ---- aH fragments (reused for Bh and Bl passes) ----
#pragma unroll
        for (int mi = 0; mi < 2; mi++) {
            const char* base = smAh + (wm + mi * 16 + g) * ROWB + koff;
            a[mi][0] = *(const uint32_t*)(base);
            a[mi][1] = *(const uint32_t*)(base + 8 * ROWB);
            a[mi][2] = *(const uint32_t*)(base + 16);
            a[mi][3] = *(const uint32_t*)(base + 8 * ROWB + 16);
        }
        // pass 0: aH x bH
#pragma unroll
        for (int nj = 0; nj < 4; nj++) {
            const char* bb = smBh + (wn + nj * 16 + g) * ROWB + koff;
            uint32_t b0 = *(const uint32_t*)(bb);
            uint32_t b1 = *(const uint32_t*)(bb + 16);
            uint32_t b2 = *(const uint32_t*)(bb + 8 * ROWB);
            uint32_t b3 = *(const uint32_t*)(bb + 8 * ROWB + 16);
#pragma unroll
            for (int mi = 0; mi < 2; mi++) {
                mma16816(acc[mi][nj * 2],     a[mi][0], a[mi][1], a[mi][2], a[mi][3], b0, b1);
                mma16816(acc[mi][nj * 2 + 1], a[mi][0], a[mi][1], a[mi][2], a[mi][3], b2, b3);
            }
        }
        // pass 1: aH x bL
#pragma unroll
        for (int nj = 0; nj < 4; nj++) {
            const char* bb = smBl + (wn + nj * 16 + g) * ROWB + koff;
            uint32_t b0 = *(const uint32_t*)(bb);
            uint32_t b1 = *(const uint32_t*)(bb + 16);
            uint32_t b2 = *(const uint32_t*)(bb + 8 * ROWB);
            uint32_t b3 = *(const uint32_t*)(bb + 8 * ROWB + 16);
#pragma unroll
            for (int mi = 0; mi < 2; mi++) {
                mma16816(acc[mi][nj * 2],     a[mi][0], a[mi][1], a[mi][2], a[mi][3], b0, b1);
                mma16816(acc[mi][nj * 2 + 1], a[mi][0], a[mi][1], a[mi][2], a[mi][3], b2, b3);
            }
        }
        // ---- aL fragments ----
#pragma unroll
        for (int mi = 0; mi < 2; mi++) {
            const char* base = smAl + (wm + mi * 16 + g) * ROWB + koff;
            a[mi][0] = *(const uint32_t*)(base);
            a[mi][1] = *(const uint32_t*)(base + 8 * ROWB);
            a[mi][2] = *(const uint32_t*)(base + 16);
            a[mi][3] = *(const uint32_t*)(base + 8 * ROWB + 16);
        }
        // pass 2: aL x bH
#pragma unroll
        for (int nj = 0; nj < 4; nj++) {
            const char* bb = smBh + (wn + nj * 16 + g) * ROWB + koff;
            uint32_t b0 = *(const uint32_t*)(bb);
            uint32_t b1 = *(const uint32_t*)(bb + 16);
            uint32_t b2 = *(const uint32_t*)(bb + 8 * ROWB);
            uint32_t b3 = *(const uint32_t*)(bb + 8 * ROWB + 16);
#pragma unroll
            for (int mi = 0; mi < 2; mi++) {
                mma16816(acc[mi][nj * 2],     a[mi][0], a[mi][1], a[mi][2], a[mi][3], b0, b1);
                mma16816(acc[mi][nj * 2 + 1], a[mi][0], a[mi][1], a[mi][2], a[mi][3], b2, b3);
            }
        }
    }
#undef LDG_CHUNKS
#undef CVT_STS

    // epilogue: c0,c1 at (m, n=2t), c2,c3 at (m+8, n=2t)
    int mrow = g;
    int ncol = t * 2;
#pragma unroll
    for (int mi = 0; mi < 2; mi++) {
        int m = m0 + wm + mi * 16 + mrow;
        if (MODE == 0) {
            float bv0 = bias[m], bv8 = bias[m + 8];
#pragma unroll
            for (int n8 = 0; n8 < 8; n8++) {
                int n = n0 + wn + n8 * 8 + ncol;
                float* c = acc[mi][n8];
                float2 lo = make_float2(fmaxf(c[0] + bv0, 0.f), fmaxf(c[1] + bv0, 0.f));
                float2 hi = make_float2(fmaxf(c[2] + bv8, 0.f), fmaxf(c[3] + bv8, 0.f));
                *(float2*)(out + (size_t)m * B_SZ + n) = lo;
                *(float2*)(out + (size_t)(m + 8) * B_SZ + n) = hi;
            }
        } else {
#pragma unroll
            for (int n8 = 0; n8 < 8; n8++) {
                int n = n0 + wn + n8 * 8 + ncol;
                float* c = acc[mi][n8];
                if (m < NOUT) {
                    atomicAdd(out + (size_t)n * NOUT + m, c[0]);
                    atomicAdd(out + (size_t)(n + 1) * NOUT + m, c[1]);
                }
                if (m + 8 < NOUT) {
                    atomicAdd(out + (size_t)n * NOUT + m + 8, c[2]);
                    atomicAdd(out + (size_t)(n + 1) * NOUT + m + 8, c[3]);
                }
            }
        }
    }
}

// ---------------------------------------------------------------------------
// Condensed layer, 2-wide batch slices: 64 KB smem -> 2 CTAs/SM, grid=256,
// occ ~100% (vs 50% at 4-wide/128KB/grid=128 which left 20 SMs idle).
// phase 0: fp32 [o][b] -> fp32 [o][b]
// phase 1: fp32 [o][b] -> fp32 [b][o] (g_a1t)
// ---------------------------------------------------------------------------
__global__ __launch_bounds__(1024, 2) void cond_kernel(int phase, const float* __restrict__ bias) {
    extern __shared__ float2 hs2[];   // [NMID]
    const float* hin = (phase == 0) ? (const float*)g_act0v : (const float*)g_act1v;
    const float4* wp = g_wf4[phase];
    int bq = blockIdx.x;              // float2 column index (b0 = 2*bq)
    int b0 = bq * 2;
    int tid = threadIdx.x;

    for (int j = tid; j < NMID; j += 1024)
        hs2[j] = *(const float2*)(hin + (size_t)j * B_SZ + b0);
    __syncthreads();

#pragma unroll
    for (int oi = 0; oi < NMID / 1024; oi++) {
        int o = oi * 1024 + tid;
        float ax = 0.f, ay = 0.f;
#pragma unroll
        for (int g = 0; g < FAN / 8; g++) {
            uint4 iv = g_if4[(size_t)g * NMID + o];
            float4 w0 = wp[(size_t)(2 * g) * NMID + o];
            float4 w1 = wp[(size_t)(2 * g + 1) * NMID + o];
            float2 h0 = hs2[iv.x & 0xffff];
            float2 h1 = hs2[iv.x >> 16];
            float2 h2 = hs2[iv.y & 0xffff];
            float2 h3 = hs2[iv.y >> 16];
            float2 h4 = hs2[iv.z & 0xffff];
            float2 h5 = hs2[iv.z >> 16];
            float2 h6 = hs2[iv.w & 0xffff];
            float2 h7 = hs2[iv.w >> 16];
            ax = fmaf(w0.x, h0.x, ax); ay = fmaf(w0.x, h0.y, ay);
            ax = fmaf(w0.y, h1.x, ax); ay = fmaf(w0.y, h1.y, ay);
            ax = fmaf(w0.z, h2.x, ax); ay = fmaf(w0.z, h2.y, ay);
            ax = fmaf(w0.w, h3.x, ax); ay = fmaf(w0.w, h3.y, ay);
            ax = fmaf(w1.x, h4.x, ax); ay = fmaf(w1.x, h4.y, ay);
            ax = fmaf(w1.y, h5.x, ax); ay = fmaf(w1.y, h5.y, ay);
            ax = fmaf(w1.z, h6.x, ax); ay = fmaf(w1.z, h6.y, ay);
            ax = fmaf(w1.w, h7.x, ax); ay = fmaf(w1.w, h7.y, ay);
        }
        float bv = bias[o];
        float2 r = make_float2(fmaxf(ax + bv, 0.f), fmaxf(ay + bv, 0.f));
        if (phase == 0) {
            *(float2*)((float*)g_act1v + (size_t)o * B_SZ + b0) = r;
        } else {
            g_a1t[(size_t)(b0 + 0) * NMID + o] = r.x;
            g_a1t[(size_t)(b0 + 1) * NMID + o] = r.y;
        }
    }
}

// ---------------------------------------------------------------------------
__global__ void init_out_kernel(const float* __restrict__ bout, float* __restrict__ out) {
    int t = blockIdx.x * blockDim.x + threadIdx.x;
    if (t < B_SZ * NOUT) out[t] = bout[t % NOUT];
}

// ---------------------------------------------------------------------------
extern "C" void kernel_launch(void* const* d_in, const int* in_sizes, int n_in,
                              void* d_out, int out_size) {
    const float* x    = (const float*)d_in[0];
    const float* Win  = (const float*)d_in[1];
    const float* bin  = (const float*)d_in[2];
    const float* Wmid = (const float*)d_in[3];
    const float* bmid = (const float*)d_in[4];
    const float* Wout = (const float*)d_in[5];
    const float* bout = (const float*)d_in[6];
    const int*   idx  = (const int*)d_in[7];    // int32 (JAX x64 disabled)
    float* out = (float*)d_out;

    cudaFuncSetAttribute(cond_kernel, cudaFuncAttributeMaxDynamicSharedMemorySize, 65536);

    // cond prep (scratch globals bound inside device code)
    prep_w_kernel<<<(NCOND * (FAN / 4) * NMID + 255) / 256, 256>>>(Wmid);
    prep_i_kernel<<<((FAN / 8) * NMID + 255) / 256, 256>>>(idx);

    // GEMM1: relu(W_in x^T + b_in) -> g_act0 fp32 [o][b]; fp32 staged, split in-kernel
    mma_gemm<0><<<dim3(B_SZ / TBN, NMID / TBM, 1), GEMM_THREADS>>>(
        Win, x, bin, nullptr, NIN / TBK);

    // condensed layers (2 batch cols per CTA, 256 CTAs, 2 CTAs/SM)
    cond_kernel<<<B_SZ / 2, 1024, 65536>>>(0, bmid);
    cond_kernel<<<B_SZ / 2, 1024, 65536>>>(1, bmid + NMID);

    // GEMM3: out[b][m] = act1 . W_out^T + b_out  (split-K=8, atomic)
    init_out_kernel<<<(B_SZ * NOUT + 255) / 256, 256>>>(bout, out);
    mma_gemm<1><<<dim3(B_SZ / TBN, MPAD / TBM, 8), GEMM_THREADS>>>(
        Wout, nullptr, nullptr, out, NMID / (TBK * 8));
}

// round 14
// speedup vs baseline: 1.1627x; 1.1627x over previous
#include <cuda_runtime.h>
#include <cuda_bf16.h>
#include <cstdint>

#define B_SZ  512
#define NIN   1024
#define NMID  8192
#define NOUT  1000
#define MPAD  1024
#define FAN   64
#define NCOND 2

// warp-MMA GEMM tiling (fp32 staged, hi/lo bf16 split at STS)
#define TBM 128
#define TBN 128
#define TBK 16            // real-K elems per chunk
#define ROWB 48           // bf16 tile row stride bytes (32B data + 16B pad; conflict-free)
#define GEMM_THREADS 256

// ---------------------------------------------------------------------------
// Scratch (static device globals; referenced ONLY inside device code --
// passing them as kernel args from host binds the host shadow, which on
// GB300/ATS silently reads zeros / writes host RAM: the R5/R6 bug)
// ---------------------------------------------------------------------------
__device__ float4 g_act0v[(size_t)NMID * B_SZ / 4];           // fp32 [o][b]
__device__ float4 g_act1v[(size_t)NMID * B_SZ / 4];           // fp32 [o][b]
__device__ float  g_a1t[(size_t)B_SZ * NMID];                 // fp32 [b][o] (cond1 out, GEMM3 B)
__device__ float4 g_wf4[NCOND][(size_t)(FAN / 4) * NMID];     // cond w packed
__device__ uint4  g_if4[(size_t)(FAN / 8) * NMID];            // cond idx packed u16

// ---------------------------------------------------------------------------
__device__ __forceinline__ void mma16816(float* d,
                                         uint32_t a0, uint32_t a1, uint32_t a2, uint32_t a3,
                                         uint32_t b0, uint32_t b1) {
    asm volatile(
        "mma.sync.aligned.m16n8k16.row.col.f32.bf16.bf16.f32 "
        "{%0,%1,%2,%3}, {%4,%5,%6,%7}, {%8,%9}, {%0,%1,%2,%3};"
        : "+f"(d[0]), "+f"(d[1]), "+f"(d[2]), "+f"(d[3])
        : "r"(a0), "r"(a1), "r"(a2), "r"(a3), "r"(b0), "r"(b1));
}
__device__ __forceinline__ void ldsm_x4(uint32_t& r0, uint32_t& r1, uint32_t& r2, uint32_t& r3,
                                        uint32_t saddr) {
    asm volatile("ldmatrix.sync.aligned.m8n8.x4.shared.b16 {%0,%1,%2,%3}, [%4];"
                 : "=r"(r0), "=r"(r1), "=r"(r2), "=r"(r3) : "r"(saddr));
}

__device__ __forceinline__ void split_bf16(float v, __nv_bfloat16& h, __nv_bfloat16& l) {
    h = __float2bfloat16(v);
    l = __float2bfloat16(v - __bfloat162float(h));
}
// split float4 into packed hi (ushort4) and lo (ushort4)
__device__ __forceinline__ void split4(float4 v, ushort4& hv, ushort4& lv) {
    __nv_bfloat16 h0, h1, h2, h3, l0, l1, l2, l3;
    split_bf16(v.x, h0, l0); split_bf16(v.y, h1, l1);
    split_bf16(v.z, h2, l2); split_bf16(v.w, h3, l3);
    hv = make_ushort4(__bfloat16_as_ushort(h0), __bfloat16_as_ushort(h1),
                      __bfloat16_as_ushort(h2), __bfloat16_as_ushort(h3));
    lv = make_ushort4(__bfloat16_as_ushort(l0), __bfloat16_as_ushort(l1),
                      __bfloat16_as_ushort(l2), __bfloat16_as_ushort(l3));
}

// ---------------------------------------------------------------------------
// cond prep
// ---------------------------------------------------------------------------
__global__ void prep_w_kernel(const float* __restrict__ Wmid) {
    int t = blockIdx.x * blockDim.x + threadIdx.x;
    if (t >= NCOND * (FAN / 4) * NMID) return;
    int phase = t / ((FAN / 4) * NMID);
    int rem = t - phase * (FAN / 4) * NMID;
    int g = rem / NMID, o = rem - g * NMID;
    const float* src = Wmid + (size_t)(phase * NMID + o) * FAN + g * 4;
    g_wf4[phase][(size_t)g * NMID + o] = make_float4(src[0], src[1], src[2], src[3]);
}
__global__ void prep_i_kernel(const int* __restrict__ idx) {
    int t = blockIdx.x * blockDim.x + threadIdx.x;
    if (t >= (FAN / 8) * NMID) return;
    int g = t / NMID, o = t - g * NMID;
    const int* src = idx + (size_t)o * FAN + g * 8;
    uint4 v;
    v.x = (unsigned)(src[0] & (NMID - 1)) | ((unsigned)(src[1] & (NMID - 1)) << 16);
    v.y = (unsigned)(src[2] & (NMID - 1)) | ((unsigned)(src[3] & (NMID - 1)) << 16);
    v.z = (unsigned)(src[4] & (NMID - 1)) | ((unsigned)(src[5] & (NMID - 1)) << 16);
    v.w = (unsigned)(src[6] & (NMID - 1)) | ((unsigned)(src[7] & (NMID - 1)) << 16);
    g_if4[(size_t)g * NMID + o] = v;
}

// ---------------------------------------------------------------------------
// warp-MMA bf16-split GEMM, fp32 inputs converted during staging; ldmatrix
// fragment loads (12 LDSM.x4 per iter vs 48 LDS.32):
//   D[m][n] = sum_k A[m][k]*B[n][k], evaluated as Ah*Bh + Ah*Bl + Al*Bh
// MODE 0: A=Win(arg) B=x(arg),  Ks=NIN,  out: g_act0[m*B_SZ+n]=relu(D+bias[m])
// MODE 1: A=Wout(arg) B=g_a1t,  Ks=NMID, out: atomicAdd(out[n*NOUT+m], D); A rows >= NOUT -> 0
// ---------------------------------------------------------------------------
template <int MODE>
__global__ __launch_bounds__(GEMM_THREADS) void mma_gemm(
    const float* __restrict__ Asrc, const float* __restrict__ Bsrc,
    const float* __restrict__ bias, float* __restrict__ outp, int kIters)
{
    const float* __restrict__ A = Asrc;
    const float* __restrict__ B = (MODE == 0) ? Bsrc : (const float*)g_a1t;
    float* out = (MODE == 0) ? (float*)g_act0v : outp;
    const int Ks = (MODE == 0) ? NIN : NMID;

    __shared__ __align__(16) char smAh[TBM * ROWB];
    __shared__ __align__(16) char smAl[TBM * ROWB];
    __shared__ __align__(16) char smBh[TBN * ROWB];
    __shared__ __align__(16) char smBl[TBN * ROWB];

    int tid = threadIdx.x;
    int wid = tid >> 5, lid = tid & 31;
    int g = lid >> 2, t = lid & 3;
    int wm = (wid >> 1) * 32;               // warp M offset in tile
    int wn = (wid & 1) * 64;                // warp N offset in tile
    int m0 = blockIdx.y * TBM;
    int n0 = blockIdx.x * TBN;
    int kk0 = blockIdx.z * kIters * TBK;

    // ldmatrix per-lane addressing: lanes 0-15 pick rows, lane>=16 picks 2nd 16B k-half
    int lrow = lid & 15;
    int lsel = lid >> 4;
    uint32_t sAh = (uint32_t)__cvta_generic_to_shared(smAh);
    uint32_t sAl = (uint32_t)__cvta_generic_to_shared(smAl);
    uint32_t sBh = (uint32_t)__cvta_generic_to_shared(smBh);
    uint32_t sBl = (uint32_t)__cvta_generic_to_shared(smBl);
    uint32_t lmoff = (uint32_t)(lrow * ROWB + lsel * 16);

    // staging: tile = 128 rows x 16 fp32 (64B) = 512 chunks of 16B; 2 per thread
    int ra0 = tid >> 2,          sa0 = (tid & 3) * 4;            // seg in floats
    int ra1 = (tid + 256) >> 2,  sa1 = ((tid + 256) & 3) * 4;

    float4 fA0, fA1, fB0, fB1;
    float acc[2][8][4] = {};

#define LDG_CHUNKS(it)                                                             \
    do {                                                                           \
        int kk = kk0 + (it) * TBK;                                                 \
        fA0 = (MODE == 1 && m0 + ra0 >= NOUT) ? make_float4(0.f, 0.f, 0.f, 0.f)    \
              : __ldg((const float4*)(A + (size_t)(m0 + ra0) * Ks + kk + sa0));    \
        fA1 = (MODE == 1 && m0 + ra1 >= NOUT) ? make_float4(0.f, 0.f, 0.f, 0.f)    \
              : __ldg((const float4*)(A + (size_t)(m0 + ra1) * Ks + kk + sa1));    \
        fB0 = __ldg((const float4*)(B + (size_t)(n0 + ra0) * Ks + kk + sa0));      \
        fB1 = __ldg((const float4*)(B + (size_t)(n0 + ra1) * Ks + kk + sa1));      \
    } while (0)

#define CVT_STS()                                                                  \
    do {                                                                           \
        ushort4 hv, lv;                                                            \
        split4(fA0, hv, lv);                                                       \
        *(ushort4*)(smAh + ra0 * ROWB + sa0 * 2) = hv;                             \
        *(ushort4*)(smAl + ra0 * ROWB + sa0 * 2) = lv;                             \
        split4(fA1, hv, lv);                                                       \
        *(ushort4*)(smAh + ra1 * ROWB + sa1 * 2) = hv;                             \
        *(ushort4*)(smAl + ra1 * ROWB + sa1 * 2) = lv;                             \
        split4(fB0, hv, lv);                                                       \
        *(ushort4*)(smBh + ra0 * ROWB + sa0 * 2) = hv;                             \
        *(ushort4*)(smBl + ra0 * ROWB + sa0 * 2) = lv;                             \
        split4(fB1, hv, lv);                                                       \
        *(ushort4*)(smBh + ra1 * ROWB + sa1 * 2) = hv;                             \
        *(ushort4*)(smBl + ra1 * ROWB + sa1 * 2) = lv;                             \
    } while (0)

    LDG_CHUNKS(0);

    for (int it = 0; it < kIters; it++) {
        __syncthreads();                    // previous compute done everywhere
        CVT_STS();
        __syncthreads();
        if (it + 1 < kIters) LDG_CHUNKS(it + 1);   // hidden under compute below

        // ---- A fragments (hi and lo), via ldmatrix.x4 ----
        // tile order: r0=rows0-7/k0, r1=rows8-15/k0, r2=rows0-7/k1, r3=rows8-15/k1
        // == PTX m16n8k16 A frag order (a0,a1,a2,a3)
        uint32_t ah[2][4], al[2][4];
#pragma unroll
        for (int mi = 0; mi < 2; mi++) {
            uint32_t base = (uint32_t)((wm + mi * 16) * ROWB) + lmoff;
            ldsm_x4(ah[mi][0], ah[mi][1], ah[mi][2], ah[mi][3], sAh + base);
            ldsm_x4(al[mi][0], al[mi][1], al[mi][2], al[mi][3], sAl + base);
        }
#pragma unroll
        for (int nj = 0; nj < 4; nj++) {
            uint32_t base = (uint32_t)((wn + nj * 16) * ROWB) + lmoff;
            uint32_t bh0, bh1, bh2, bh3, bl0, bl1, bl2, bl3;
            ldsm_x4(bh0, bh1, bh2, bh3, sBh + base);
            ldsm_x4(bl0, bl1, bl2, bl3, sBl + base);
            // B n-subtile 0 = (r0, r2); n-subtile 1 = (r1, r3)
#pragma unroll
            for (int mi = 0; mi < 2; mi++) {
                // aH x bH
                mma16816(acc[mi][nj * 2],     ah[mi][0], ah[mi][1], ah[mi][2], ah[mi][3], bh0, bh2);
                mma16816(acc[mi][nj * 2 + 1], ah[mi][0], ah[mi][1], ah[mi][2], ah[mi][3], bh1, bh3);
                // aH x bL
                mma16816(acc[mi][nj * 2],     ah[mi][0], ah[mi][1], ah[mi][2], ah[mi][3], bl0, bl2);
                mma16816(acc[mi][nj * 2 + 1], ah[mi][0], ah[mi][1], ah[mi][2], ah[mi][3], bl1, bl3);
                // aL x bH
                mma16816(acc[mi][nj * 2],     al[mi][0], al[mi][1], al[mi][2], al[mi][3], bh0, bh2);
                mma16816(acc[mi][nj * 2 + 1], al[mi][0], al[mi][1], al[mi][2], al[mi][3], bh1, bh3);
            }
        }
    }
#undef LDG_CHUNKS
#undef CVT_STS

    // epilogue: c0,c1 at (m, n=2t), c2,c3 at (m+8, n=2t)
    int mrow = g;
    int ncol = t * 2;
#pragma unroll
    for (int mi = 0; mi < 2; mi++) {
        int m = m0 + wm + mi * 16 + mrow;
        if (MODE == 0) {
            float bv0 = bias[m], bv8 = bias[m + 8];
#pragma unroll
            for (int n8 = 0; n8 < 8; n8++) {
                int n = n0 + wn + n8 * 8 + ncol;
                float* c = acc[mi][n8];
                float2 lo = make_float2(fmaxf(c[0] + bv0, 0.f), fmaxf(c[1] + bv0, 0.f));
                float2 hi = make_float2(fmaxf(c[2] + bv8, 0.f), fmaxf(c[3] + bv8, 0.f));
                *(float2*)(out + (size_t)m * B_SZ + n) = lo;
                *(float2*)(out + (size_t)(m + 8) * B_SZ + n) = hi;
            }
        } else {
#pragma unroll
            for (int n8 = 0; n8 < 8; n8++) {
                int n = n0 + wn + n8 * 8 + ncol;
                float* c = acc[mi][n8];
                if (m < NOUT) {
                    atomicAdd(out + (size_t)n * NOUT + m, c[0]);
                    atomicAdd(out + (size_t)(n + 1) * NOUT + m, c[1]);
                }
                if (m + 8 < NOUT) {
                    atomicAdd(out + (size_t)n * NOUT + m + 8, c[2]);
                    atomicAdd(out + (size_t)(n + 1) * NOUT + m + 8, c[3]);
                }
            }
        }
    }
}

// ---------------------------------------------------------------------------
// Condensed layer (R10-proven: 4-wide float4 slices, 128 KB smem, grid=128).
// phase 0: fp32 [o][b] -> fp32 [o][b]
// phase 1: fp32 [o][b] -> fp32 [b][o] (g_a1t)
// ---------------------------------------------------------------------------
__global__ __launch_bounds__(1024) void cond_kernel(int phase, const float* __restrict__ bias) {
    extern __shared__ float4 hs[];   // [NMID]
    const float4* hin = (phase == 0) ? g_act0v : g_act1v;
    const float4* wp = g_wf4[phase];
    int bq = blockIdx.x;
    int b0 = bq * 4;
    int tid = threadIdx.x;

    for (int j = tid; j < NMID; j += 1024)
        hs[j] = hin[(size_t)j * (B_SZ / 4) + bq];
    __syncthreads();

#pragma unroll
    for (int oi = 0; oi < NMID / 1024; oi++) {
        int o = oi * 1024 + tid;
        float ax = 0.f, ay = 0.f, az = 0.f, aw = 0.f;
#pragma unroll
        for (int g = 0; g < FAN / 8; g++) {
            uint4 iv = g_if4[(size_t)g * NMID + o];
            float4 w0 = wp[(size_t)(2 * g) * NMID + o];
            float4 w1 = wp[(size_t)(2 * g + 1) * NMID + o];
            float4 h0 = hs[iv.x & 0xffff];
            float4 h1 = hs[iv.x >> 16];
            float4 h2 = hs[iv.y & 0xffff];
            float4 h3 = hs[iv.y >> 16];
            float4 h4 = hs[iv.z & 0xffff];
            float4 h5 = hs[iv.z >> 16];
            float4 h6 = hs[iv.w & 0xffff];
            float4 h7 = hs[iv.w >> 16];
            ax = fmaf(w0.x, h0.x, ax); ay = fmaf(w0.x, h0.y, ay);
            az = fmaf(w0.x, h0.z, az); aw = fmaf(w0.x, h0.w, aw);
            ax = fmaf(w0.y, h1.x, ax); ay = fmaf(w0.y, h1.y, ay);
            az = fmaf(w0.y, h1.z, az); aw = fmaf(w0.y, h1.w, aw);
            ax = fmaf(w0.z, h2.x, ax); ay = fmaf(w0.z, h2.y, ay);
            az = fmaf(w0.z, h2.z, az); aw = fmaf(w0.z, h2.w, aw);
            ax = fmaf(w0.w, h3.x, ax); ay = fmaf(w0.w, h3.y, ay);
            az = fmaf(w0.w, h3.z, az); aw = fmaf(w0.w, h3.w, aw);
            ax = fmaf(w1.x, h4.x, ax); ay = fmaf(w1.x, h4.y, ay);
            az = fmaf(w1.x, h4.z, az); aw = fmaf(w1.x, h4.w, aw);
            ax = fmaf(w1.y, h5.x, ax); ay = fmaf(w1.y, h5.y, ay);
            az = fmaf(w1.y, h5.z, az); aw = fmaf(w1.y, h5.w, aw);
            ax = fmaf(w1.z, h6.x, ax); ay = fmaf(w1.z, h6.y, ay);
            az = fmaf(w1.z, h6.z, az); aw = fmaf(w1.z, h6.w, aw);
            ax = fmaf(w1.w, h7.x, ax); ay = fmaf(w1.w, h7.y, ay);
            az = fmaf(w1.w, h7.z, az); aw = fmaf(w1.w, h7.w, aw);
        }
        float bv = bias[o];
        float4 r;
        r.x = fmaxf(ax + bv, 0.f); r.y = fmaxf(ay + bv, 0.f);
        r.z = fmaxf(az + bv, 0.f); r.w = fmaxf(aw + bv, 0.f);
        if (phase == 0) {
            g_act1v[(size_t)o * (B_SZ / 4) + bq] = r;
        } else {
            g_a1t[(size_t)(b0 + 0) * NMID + o] = r.x;
            g_a1t[(size_t)(b0 + 1) * NMID + o] = r.y;
            g_a1t[(size_t)(b0 + 2) * NMID + o] = r.z;
            g_a1t[(size_t)(b0 + 3) * NMID + o] = r.w;
        }
    }
}

// ---------------------------------------------------------------------------
__global__ void init_out_kernel(const float* __restrict__ bout, float* __restrict__ out) {
    int t = blockIdx.x * blockDim.x + threadIdx.x;
    if (t < B_SZ * NOUT) out[t] = bout[t % NOUT];
}

// ---------------------------------------------------------------------------
extern "C" void kernel_launch(void* const* d_in, const int* in_sizes, int n_in,
                              void* d_out, int out_size) {
    const float* x    = (const float*)d_in[0];
    const float* Win  = (const float*)d_in[1];
    const float* bin  = (const float*)d_in[2];
    const float* Wmid = (const float*)d_in[3];
    const float* bmid = (const float*)d_in[4];
    const float* Wout = (const float*)d_in[5];
    const float* bout = (const float*)d_in[6];
    const int*   idx  = (const int*)d_in[7];    // int32 (JAX x64 disabled)
    float* out = (float*)d_out;

    cudaFuncSetAttribute(cond_kernel, cudaFuncAttributeMaxDynamicSharedMemorySize, 131072);

    // cond prep (scratch globals bound inside device code)
    prep_w_kernel<<<(NCOND * (FAN / 4) * NMID + 255) / 256, 256>>>(Wmid);
    prep_i_kernel<<<((FAN / 8) * NMID + 255) / 256, 256>>>(idx);

    // GEMM1: relu(W_in x^T + b_in) -> g_act0 fp32 [o][b]; fp32 staged, split in-kernel
    mma_gemm<0><<<dim3(B_SZ / TBN, NMID / TBM, 1), GEMM_THREADS>>>(
        Win, x, bin, nullptr, NIN / TBK);

    // condensed layers (4 batch cols per CTA, 128 CTAs)
    cond_kernel<<<B_SZ / 4, 1024, 131072>>>(0, bmid);
    cond_kernel<<<B_SZ / 4, 1024, 131072>>>(1, bmid + NMID);

    // GEMM3: out[b][m] = act1 . W_out^T + b_out  (split-K=8, atomic)
    init_out_kernel<<<(B_SZ * NOUT + 255) / 256, 256>>>(bout, out);
    mma_gemm<1><<<dim3(B_SZ / TBN, MPAD / TBM, 8), GEMM_THREADS>>>(
        Wout, nullptr, nullptr, out, NMID / (TBK * 8));
}

// round 15
// speedup vs baseline: 1.3887x; 1.1944x over previous
#include <cuda_runtime.h>
#include <cuda_bf16.h>
#include <cuda_fp16.h>
#include <cstdint>

#define B_SZ  512
#define NIN   1024
#define NMID  8192
#define NOUT  1000
#define MPAD  1024
#define FAN   64
#define NCOND 2

// warp-MMA GEMM tiling (fp32 staged, hi/lo bf16 split at STS) -- R10-proven
#define TBM 128
#define TBN 128
#define TBK 16            // real-K elems per chunk
#define ROWB 48           // bf16 tile row stride bytes (32B data + 16B pad; conflict-free)
#define GEMM_THREADS 256

// ---------------------------------------------------------------------------
// Scratch (static device globals; referenced ONLY inside device code --
// passing them as kernel args from host binds the host shadow, which on
// GB300/ATS silently reads zeros / writes host RAM: the R5/R6 bug)
// ---------------------------------------------------------------------------
__device__ float4 g_act0v[(size_t)NMID * B_SZ / 4];           // fp32 [o][b]
__device__ float4 g_act1v[(size_t)NMID * B_SZ / 4];           // fp32 [o][b]
__device__ float  g_a1t[(size_t)B_SZ * NMID];                 // fp32 [b][o] (cond1 out, GEMM3 B)
__device__ float4 g_wf4[NCOND][(size_t)(FAN / 4) * NMID];     // cond w packed
__device__ uint4  g_if4[(size_t)(FAN / 8) * NMID];            // cond idx packed u16

// ---------------------------------------------------------------------------
__device__ __forceinline__ void mma16816(float* d,
                                         uint32_t a0, uint32_t a1, uint32_t a2, uint32_t a3,
                                         uint32_t b0, uint32_t b1) {
    asm volatile(
        "mma.sync.aligned.m16n8k16.row.col.f32.bf16.bf16.f32 "
        "{%0,%1,%2,%3}, {%4,%5,%6,%7}, {%8,%9}, {%0,%1,%2,%3};"
        : "+f"(d[0]), "+f"(d[1]), "+f"(d[2]), "+f"(d[3])
        : "r"(a0), "r"(a1), "r"(a2), "r"(a3), "r"(b0), "r"(b1));
}

__device__ __forceinline__ void split_bf16(float v, __nv_bfloat16& h, __nv_bfloat16& l) {
    h = __float2bfloat16(v);
    l = __float2bfloat16(v - __bfloat162float(h));
}
// split float4 into packed hi (ushort4) and lo (ushort4)
__device__ __forceinline__ void split4(float4 v, ushort4& hv, ushort4& lv) {
    __nv_bfloat16 h0, h1, h2, h3, l0, l1, l2, l3;
    split_bf16(v.x, h0, l0); split_bf16(v.y, h1, l1);
    split_bf16(v.z, h2, l2); split_bf16(v.w, h3, l3);
    hv = make_ushort4(__bfloat16_as_ushort(h0), __bfloat16_as_ushort(h1),
                      __bfloat16_as_ushort(h2), __bfloat16_as_ushort(h3));
    lv = make_ushort4(__bfloat16_as_ushort(l0), __bfloat16_as_ushort(l1),
                      __bfloat16_as_ushort(l2), __bfloat16_as_ushort(l3));
}

// ---------------------------------------------------------------------------
// cond prep
// ---------------------------------------------------------------------------
__global__ void prep_w_kernel(const float* __restrict__ Wmid) {
    int t = blockIdx.x * blockDim.x + threadIdx.x;
    if (t >= NCOND * (FAN / 4) * NMID) return;
    int phase = t / ((FAN / 4) * NMID);
    int rem = t - phase * (FAN / 4) * NMID;
    int g = rem / NMID, o = rem - g * NMID;
    const float* src = Wmid + (size_t)(phase * NMID + o) * FAN + g * 4;
    g_wf4[phase][(size_t)g * NMID + o] = make_float4(src[0], src[1], src[2], src[3]);
}
__global__ void prep_i_kernel(const int* __restrict__ idx) {
    int t = blockIdx.x * blockDim.x + threadIdx.x;
    if (t >= (FAN / 8) * NMID) return;
    int g = t / NMID, o = t - g * NMID;
    const int* src = idx + (size_t)o * FAN + g * 8;
    uint4 v;
    v.x = (unsigned)(src[0] & (NMID - 1)) | ((unsigned)(src[1] & (NMID - 1)) << 16);
    v.y = (unsigned)(src[2] & (NMID - 1)) | ((unsigned)(src[3] & (NMID - 1)) << 16);
    v.z = (unsigned)(src[4] & (NMID - 1)) | ((unsigned)(src[5] & (NMID - 1)) << 16);
    v.w = (unsigned)(src[6] & (NMID - 1)) | ((unsigned)(src[7] & (NMID - 1)) << 16);
    g_if4[(size_t)g * NMID + o] = v;
}

// ---------------------------------------------------------------------------
// warp-MMA bf16-split GEMM (R10-proven), fp32 inputs converted during staging:
//   D[m][n] = sum_k A[m][k]*B[n][k], evaluated as Ah*Bh + Ah*Bl + Al*Bh
// MODE 0: A=Win(arg) B=x(arg),  Ks=NIN,  out: g_act0[m*B_SZ+n]=relu(D+bias[m])
// MODE 1: A=Wout(arg) B=g_a1t,  Ks=NMID, out: atomicAdd(out[n*NOUT+m], D); A rows >= NOUT -> 0
// ---------------------------------------------------------------------------
template <int MODE>
__global__ __launch_bounds__(GEMM_THREADS) void mma_gemm(
    const float* __restrict__ Asrc, const float* __restrict__ Bsrc,
    const float* __restrict__ bias, float* __restrict__ outp, int kIters)
{
    const float* __restrict__ A = Asrc;
    const float* __restrict__ B = (MODE == 0) ? Bsrc : (const float*)g_a1t;
    float* out = (MODE == 0) ? (float*)g_act0v : outp;
    const int Ks = (MODE == 0) ? NIN : NMID;

    __shared__ __align__(16) char smAh[TBM * ROWB];
    __shared__ __align__(16) char smAl[TBM * ROWB];
    __shared__ __align__(16) char smBh[TBN * ROWB];
    __shared__ __align__(16) char smBl[TBN * ROWB];

    int tid = threadIdx.x;
    int wid = tid >> 5, lid = tid & 31;
    int g = lid >> 2, t = lid & 3;
    int wm = (wid >> 1) * 32;               // warp M offset in tile
    int wn = (wid & 1) * 64;                // warp N offset in tile
    int m0 = blockIdx.y * TBM;
    int n0 = blockIdx.x * TBN;
    int kk0 = blockIdx.z * kIters * TBK;

    // staging: tile = 128 rows x 16 fp32 (64B) = 512 chunks of 16B; 2 per thread
    int ra0 = tid >> 2,          sa0 = (tid & 3) * 4;            // seg in floats
    int ra1 = (tid + 256) >> 2,  sa1 = ((tid + 256) & 3) * 4;

    float4 fA0, fA1, fB0, fB1;
    float acc[2][8][4] = {};

#define LDG_CHUNKS(it)                                                             \
    do {                                                                           \
        int kk = kk0 + (it) * TBK;                                                 \
        fA0 = (MODE == 1 && m0 + ra0 >= NOUT) ? make_float4(0.f, 0.f, 0.f, 0.f)    \
              : __ldg((const float4*)(A + (size_t)(m0 + ra0) * Ks + kk + sa0));    \
        fA1 = (MODE == 1 && m0 + ra1 >= NOUT) ? make_float4(0.f, 0.f, 0.f, 0.f)    \
              : __ldg((const float4*)(A + (size_t)(m0 + ra1) * Ks + kk + sa1));    \
        fB0 = __ldg((const float4*)(B + (size_t)(n0 + ra0) * Ks + kk + sa0));      \
        fB1 = __ldg((const float4*)(B + (size_t)(n0 + ra1) * Ks + kk + sa1));      \
    } while (0)

#define CVT_STS()                                                                  \
    do {                                                                           \
        ushort4 hv, lv;                                                            \
        split4(fA0, hv, lv);                                                       \
        *(ushort4*)(smAh + ra0 * ROWB + sa0 * 2) = hv;                             \
        *(ushort4*)(smAl + ra0 * ROWB + sa0 * 2) = lv;                             \
        split4(fA1, hv, lv);                                                       \
        *(ushort4*)(smAh + ra1 * ROWB + sa1 * 2) = hv;                             \
        *(ushort4*)(smAl + ra1 * ROWB + sa1 * 2) = lv;                             \
        split4(fB0, hv, lv);                                                       \
        *(ushort4*)(smBh + ra0 * ROWB + sa0 * 2) = hv;                             \
        *(ushort4*)(smBl + ra0 * ROWB + sa0 * 2) = lv;                             \
        split4(fB1, hv, lv);                                                       \
        *(ushort4*)(smBh + ra1 * ROWB + sa1 * 2) = hv;                             \
        *(ushort4*)(smBl + ra1 * ROWB + sa1 * 2) = lv;                             \
    } while (0)

    LDG_CHUNKS(0);

    int koff = 4 * t;                       // byte offset in 32B bf16 row
    for (int it = 0; it < kIters; it++) {
        __syncthreads();                    // previous compute done everywhere
        CVT_STS();
        __syncthreads();
        if (it + 1 < kIters) LDG_CHUNKS(it + 1);   // hidden under compute below

        uint32_t a[2][4];
        // ---- aH fragments (reused for Bh and Bl passes) ----
#pragma unroll
        for (int mi = 0; mi < 2; mi++) {
            const char* base = smAh + (wm + mi * 16 + g) * ROWB + koff;
            a[mi][0] = *(const uint32_t*)(base);
            a[mi][1] = *(const uint32_t*)(base + 8 * ROWB);
            a[mi][2] = *(const uint32_t*)(base + 16);
            a[mi][3] = *(const uint32_t*)(base + 8 * ROWB + 16);
        }
        // pass 0: aH x bH
#pragma unroll
        for (int nj = 0; nj < 4; nj++) {
            const char* bb = smBh + (wn + nj * 16 + g) * ROWB + koff;
            uint32_t b0 = *(const uint32_t*)(bb);
            uint32_t b1 = *(const uint32_t*)(bb + 16);
            uint32_t b2 = *(const uint32_t*)(bb + 8 * ROWB);
            uint32_t b3 = *(const uint32_t*)(bb + 8 * ROWB + 16);
#pragma unroll
            for (int mi = 0; mi < 2; mi++) {
                mma16816(acc[mi][nj * 2],     a[mi][0], a[mi][1], a[mi][2], a[mi][3], b0, b1);
                mma16816(acc[mi][nj * 2 + 1], a[mi][0], a[mi][1], a[mi][2], a[mi][3], b2, b3);
            }
        }
        // pass 1: aH x bL
#pragma unroll
        for (int nj = 0; nj < 4; nj++) {
            const char* bb = smBl + (wn + nj * 16 + g) * ROWB + koff;
            uint32_t b0 = *(const uint32_t*)(bb);
            uint32_t b1 = *(const uint32_t*)(bb + 16);
            uint32_t b2 = *(const uint32_t*)(bb + 8 * ROWB);
            uint32_t b3 = *(const uint32_t*)(bb + 8 * ROWB + 16);
#pragma unroll
            for (int mi = 0; mi < 2; mi++) {
                mma16816(acc[mi][nj * 2],     a[mi][0], a[mi][1], a[mi][2], a[mi][3], b0, b1);
                mma16816(acc[mi][nj * 2 + 1], a[mi][0], a[mi][1], a[mi][2], a[mi][3], b2, b3);
            }
        }
        // ---- aL fragments ----
#pragma unroll
        for (int mi = 0; mi < 2; mi++) {
            const char* base = smAl + (wm + mi * 16 + g) * ROWB + koff;
            a[mi][0] = *(const uint32_t*)(base);
            a[mi][1] = *(const uint32_t*)(base + 8 * ROWB);
            a[mi][2] = *(const uint32_t*)(base + 16);
            a[mi][3] = *(const uint32_t*)(base + 8 * ROWB + 16);
        }
        // pass 2: aL x bH
#pragma unroll
        for (int nj = 0; nj < 4; nj++) {
            const char* bb = smBh + (wn + nj * 16 + g) * ROWB + koff;
            uint32_t b0 = *(const uint32_t*)(bb);
            uint32_t b1 = *(const uint32_t*)(bb + 16);
            uint32_t b2 = *(const uint32_t*)(bb + 8 * ROWB);
            uint32_t b3 = *(const uint32_t*)(bb + 8 * ROWB + 16);
#pragma unroll
            for (int mi = 0; mi < 2; mi++) {
                mma16816(acc[mi][nj * 2],     a[mi][0], a[mi][1], a[mi][2], a[mi][3], b0, b1);
                mma16816(acc[mi][nj * 2 + 1], a[mi][0], a[mi][1], a[mi][2], a[mi][3], b2, b3);
            }
        }
    }
#undef LDG_CHUNKS
#undef CVT_STS

    // epilogue: c0,c1 at (m, n=2t), c2,c3 at (m+8, n=2t)
    int mrow = g;
    int ncol = t * 2;
#pragma unroll
    for (int mi = 0; mi < 2; mi++) {
        int m = m0 + wm + mi * 16 + mrow;
        if (MODE == 0) {
            float bv0 = bias[m], bv8 = bias[m + 8];
#pragma unroll
            for (int n8 = 0; n8 < 8; n8++) {
                int n = n0 + wn + n8 * 8 + ncol;
                float* c = acc[mi][n8];
                float2 lo = make_float2(fmaxf(c[0] + bv0, 0.f), fmaxf(c[1] + bv0, 0.f));
                float2 hi = make_float2(fmaxf(c[2] + bv8, 0.f), fmaxf(c[3] + bv8, 0.f));
                *(float2*)(out + (size_t)m * B_SZ + n) = lo;
                *(float2*)(out + (size_t)(m + 8) * B_SZ + n) = hi;
            }
        } else {
#pragma unroll
            for (int n8 = 0; n8 < 8; n8++) {
                int n = n0 + wn + n8 * 8 + ncol;
                float* c = acc[mi][n8];
                if (m < NOUT) {
                    atomicAdd(out + (size_t)n * NOUT + m, c[0]);
                    atomicAdd(out + (size_t)(n + 1) * NOUT + m, c[1]);
                }
                if (m + 8 < NOUT) {
                    atomicAdd(out + (size_t)n * NOUT + m + 8, c[2]);
                    atomicAdd(out + (size_t)(n + 1) * NOUT + m + 8, c[3]);
                }
            }
        }
    }
}

// ---------------------------------------------------------------------------
// Condensed layer with fp16 smem staging: 8 B per gather (LDS.64) instead of
// 16 B -> smem crossbar traffic halves (cond is crossbar-bound: L1=78%).
// Activations are O(1); fp16 rounding adds ~1e-4 end-to-end (threshold 1e-3).
// phase 0: fp32 [o][b] -> fp32 [o][b]
// phase 1: fp32 [o][b] -> fp32 [b][o] (g_a1t)
// ---------------------------------------------------------------------------
__global__ __launch_bounds__(1024) void cond_kernel(int phase, const float* __restrict__ bias) {
    extern __shared__ uint2 hsh[];   // [NMID], 4 halves each
    const float4* hin = (phase == 0) ? g_act0v : g_act1v;
    const float4* wp = g_wf4[phase];
    int bq = blockIdx.x;
    int b0 = bq * 4;
    int tid = threadIdx.x;

    for (int j = tid; j < NMID; j += 1024) {
        float4 v = hin[(size_t)j * (B_SZ / 4) + bq];
        __half2 p01 = __floats2half2_rn(v.x, v.y);
        __half2 p23 = __floats2half2_rn(v.z, v.w);
        uint2 u;
        u.x = *(uint32_t*)&p01;
        u.y = *(uint32_t*)&p23;
        hsh[j] = u;
    }
    __syncthreads();

#pragma unroll
    for (int oi = 0; oi < NMID / 1024; oi++) {
        int o = oi * 1024 + tid;
        float ax = 0.f, ay = 0.f, az = 0.f, aw = 0.f;
#pragma unroll
        for (int g = 0; g < FAN / 8; g++) {
            uint4 iv = g_if4[(size_t)g * NMID + o];
            float4 w0 = wp[(size_t)(2 * g) * NMID + o];
            float4 w1 = wp[(size_t)(2 * g + 1) * NMID + o];
            uint2 p0 = hsh[iv.x & 0xffff];
            uint2 p1 = hsh[iv.x >> 16];
            uint2 p2 = hsh[iv.y & 0xffff];
            uint2 p3 = hsh[iv.y >> 16];
            uint2 p4 = hsh[iv.z & 0xffff];
            uint2 p5 = hsh[iv.z >> 16];
            uint2 p6 = hsh[iv.w & 0xffff];
            uint2 p7 = hsh[iv.w >> 16];
#define ACC(p, wv)                                                        \
            {                                                             \
                float2 f01 = __half22float2(*(__half2*)&(p).x);           \
                float2 f23 = __half22float2(*(__half2*)&(p).y);           \
                ax = fmaf(wv, f01.x, ax); ay = fmaf(wv, f01.y, ay);       \
                az = fmaf(wv, f23.x, az); aw = fmaf(wv, f23.y, aw);       \
            }
            ACC(p0, w0.x) ACC(p1, w0.y) ACC(p2, w0.z) ACC(p3, w0.w)
            ACC(p4, w1.x) ACC(p5, w1.y) ACC(p6, w1.z) ACC(p7, w1.w)
#undef ACC
        }
        float bv = bias[o];
        float4 r;
        r.x = fmaxf(ax + bv, 0.f); r.y = fmaxf(ay + bv, 0.f);
        r.z = fmaxf(az + bv, 0.f); r.w = fmaxf(aw + bv, 0.f);
        if (phase == 0) {
            g_act1v[(size_t)o * (B_SZ / 4) + bq] = r;
        } else {
            g_a1t[(size_t)(b0 + 0) * NMID + o] = r.x;
            g_a1t[(size_t)(b0 + 1) * NMID + o] = r.y;
            g_a1t[(size_t)(b0 + 2) * NMID + o] = r.z;
            g_a1t[(size_t)(b0 + 3) * NMID + o] = r.w;
        }
    }
}

// ---------------------------------------------------------------------------
__global__ void init_out_kernel(const float* __restrict__ bout, float* __restrict__ out) {
    int t = blockIdx.x * blockDim.x + threadIdx.x;
    if (t < B_SZ * NOUT) out[t] = bout[t % NOUT];
}

// ---------------------------------------------------------------------------
extern "C" void kernel_launch(void* const* d_in, const int* in_sizes, int n_in,
                              void* d_out, int out_size) {
    const float* x    = (const float*)d_in[0];
    const float* Win  = (const float*)d_in[1];
    const float* bin  = (const float*)d_in[2];
    const float* Wmid = (const float*)d_in[3];
    const float* bmid = (const float*)d_in[4];
    const float* Wout = (const float*)d_in[5];
    const float* bout = (const float*)d_in[6];
    const int*   idx  = (const int*)d_in[7];    // int32 (JAX x64 disabled)
    float* out = (float*)d_out;

    cudaFuncSetAttribute(cond_kernel, cudaFuncAttributeMaxDynamicSharedMemorySize, 65536);

    // cond prep (scratch globals bound inside device code)
    prep_w_kernel<<<(NCOND * (FAN / 4) * NMID + 255) / 256, 256>>>(Wmid);
    prep_i_kernel<<<((FAN / 8) * NMID + 255) / 256, 256>>>(idx);

    // GEMM1: relu(W_in x^T + b_in) -> g_act0 fp32 [o][b]; fp32 staged, split in-kernel
    mma_gemm<0><<<dim3(B_SZ / TBN, NMID / TBM, 1), GEMM_THREADS>>>(
        Win, x, bin, nullptr, NIN / TBK);

    // condensed layers (4 batch cols per CTA, 128 CTAs, fp16 smem staging)
    cond_kernel<<<B_SZ / 4, 1024, 65536>>>(0, bmid);
    cond_kernel<<<B_SZ / 4, 1024, 65536>>>(1, bmid + NMID);

    // GEMM3: out[b][m] = act1 . W_out^T + b_out  (split-K=8, atomic)
    init_out_kernel<<<(B_SZ * NOUT + 255) / 256, 256>>>(bout, out);
    mma_gemm<1><<<dim3(B_SZ / TBN, MPAD / TBM, 8), GEMM_THREADS>>>(
        Wout, nullptr, nullptr, out, NMID / (TBK * 8));
}

// round 16
// speedup vs baseline: 1.4286x; 1.0287x over previous
#include <cuda_runtime.h>
#include <cuda_bf16.h>
#include <cuda_fp16.h>
#include <cstdint>

#define B_SZ  512
#define NIN   1024
#define NMID  8192
#define NOUT  1000
#define MPAD  1024
#define FAN   64
#define NCOND 2

// warp-MMA GEMM tiling (fp32 staged, hi/lo bf16 split at STS) -- R10-proven
#define TBM 128
#define TBN 128
#define TBK 16            // real-K elems per chunk
#define ROWB 48           // bf16 tile row stride bytes (32B data + 16B pad; conflict-free)
#define GEMM_THREADS 256

// ---------------------------------------------------------------------------
// Scratch (static device globals; referenced ONLY inside device code --
// passing them as kernel args from host binds the host shadow, which on
// GB300/ATS silently reads zeros / writes host RAM: the R5/R6 bug)
// ---------------------------------------------------------------------------
__device__ float4 g_act0v[(size_t)NMID * B_SZ / 4];           // fp32 [o][b]
__device__ float4 g_act1v[(size_t)NMID * B_SZ / 4];           // fp32 [o][b]
__device__ float  g_a1t[(size_t)B_SZ * NMID];                 // fp32 [b][o] (cond1 out, GEMM3 B)
__device__ uint4  g_pk[NCOND][(size_t)(FAN / 4) * NMID];      // cond meta: 4x (fp16 w | u16 idx)

// ---------------------------------------------------------------------------
__device__ __forceinline__ void mma16816(float* d,
                                         uint32_t a0, uint32_t a1, uint32_t a2, uint32_t a3,
                                         uint32_t b0, uint32_t b1) {
    asm volatile(
        "mma.sync.aligned.m16n8k16.row.col.f32.bf16.bf16.f32 "
        "{%0,%1,%2,%3}, {%4,%5,%6,%7}, {%8,%9}, {%0,%1,%2,%3};"
        : "+f"(d[0]), "+f"(d[1]), "+f"(d[2]), "+f"(d[3])
        : "r"(a0), "r"(a1), "r"(a2), "r"(a3), "r"(b0), "r"(b1));
}

__device__ __forceinline__ void split_bf16(float v, __nv_bfloat16& h, __nv_bfloat16& l) {
    h = __float2bfloat16(v);
    l = __float2bfloat16(v - __bfloat162float(h));
}
// split float4 into packed hi (ushort4) and lo (ushort4)
__device__ __forceinline__ void split4(float4 v, ushort4& hv, ushort4& lv) {
    __nv_bfloat16 h0, h1, h2, h3, l0, l1, l2, l3;
    split_bf16(v.x, h0, l0); split_bf16(v.y, h1, l1);
    split_bf16(v.z, h2, l2); split_bf16(v.w, h3, l3);
    hv = make_ushort4(__bfloat16_as_ushort(h0), __bfloat16_as_ushort(h1),
                      __bfloat16_as_ushort(h2), __bfloat16_as_ushort(h3));
    lv = make_ushort4(__bfloat16_as_ushort(l0), __bfloat16_as_ushort(l1),
                      __bfloat16_as_ushort(l2), __bfloat16_as_ushort(l3));
}

// ---------------------------------------------------------------------------
// cond prep: pack (fp16 w | u16 idx) into one uint per f; uint4 = 4 f's.
// f-major, o-contiguous: g_pk[phase][g4 * NMID + o].
// ---------------------------------------------------------------------------
__global__ void prep_pk_kernel(const float* __restrict__ Wmid, const int* __restrict__ idx) {
    int t = blockIdx.x * blockDim.x + threadIdx.x;
    if (t >= NCOND * (FAN / 4) * NMID) return;
    int phase = t / ((FAN / 4) * NMID);
    int rem = t - phase * (FAN / 4) * NMID;
    int g4 = rem / NMID, o = rem - g4 * NMID;
    const float* wsrc = Wmid + (size_t)(phase * NMID + o) * FAN + g4 * 4;
    const int*   isrc = idx + (size_t)o * FAN + g4 * 4;
    uint4 v;
    v.x = (unsigned)(isrc[0] & (NMID - 1)) |
          ((uint32_t)__half_as_ushort(__float2half_rn(wsrc[0])) << 16);
    v.y = (unsigned)(isrc[1] & (NMID - 1)) |
          ((uint32_t)__half_as_ushort(__float2half_rn(wsrc[1])) << 16);
    v.z = (unsigned)(isrc[2] & (NMID - 1)) |
          ((uint32_t)__half_as_ushort(__float2half_rn(wsrc[2])) << 16);
    v.w = (unsigned)(isrc[3] & (NMID - 1)) |
          ((uint32_t)__half_as_ushort(__float2half_rn(wsrc[3])) << 16);
    g_pk[phase][(size_t)g4 * NMID + o] = v;
}

// ---------------------------------------------------------------------------
// warp-MMA bf16-split GEMM (R10-proven), fp32 inputs converted during staging:
//   D[m][n] = sum_k A[m][k]*B[n][k], evaluated as Ah*Bh + Ah*Bl + Al*Bh
// MODE 0: A=Win(arg) B=x(arg),  Ks=NIN,  out: g_act0[m*B_SZ+n]=relu(D+bias[m])
// MODE 1: A=Wout(arg) B=g_a1t,  Ks=NMID, out: atomicAdd(out[n*NOUT+m], D); A rows >= NOUT -> 0
// ---------------------------------------------------------------------------
template <int MODE>
__global__ __launch_bounds__(GEMM_THREADS) void mma_gemm(
    const float* __restrict__ Asrc, const float* __restrict__ Bsrc,
    const float* __restrict__ bias, float* __restrict__ outp, int kIters)
{
    const float* __restrict__ A = Asrc;
    const float* __restrict__ B = (MODE == 0) ? Bsrc : (const float*)g_a1t;
    float* out = (MODE == 0) ? (float*)g_act0v : outp;
    const int Ks = (MODE == 0) ? NIN : NMID;

    __shared__ __align__(16) char smAh[TBM * ROWB];
    __shared__ __align__(16) char smAl[TBM * ROWB];
    __shared__ __align__(16) char smBh[TBN * ROWB];
    __shared__ __align__(16) char smBl[TBN * ROWB];

    int tid = threadIdx.x;
    int wid = tid >> 5, lid = tid & 31;
    int g = lid >> 2, t = lid & 3;
    int wm = (wid >> 1) * 32;               // warp M offset in tile
    int wn = (wid & 1) * 64;                // warp N offset in tile
    int m0 = blockIdx.y * TBM;
    int n0 = blockIdx.x * TBN;
    int kk0 = blockIdx.z * kIters * TBK;

    // staging: tile = 128 rows x 16 fp32 (64B) = 512 chunks of 16B; 2 per thread
    int ra0 = tid >> 2,          sa0 = (tid & 3) * 4;            // seg in floats
    int ra1 = (tid + 256) >> 2,  sa1 = ((tid + 256) & 3) * 4;

    float4 fA0, fA1, fB0, fB1;
    float acc[2][8][4] = {};

#define LDG_CHUNKS(it)                                                             \
    do {                                                                           \
        int kk = kk0 + (it) * TBK;                                                 \
        fA0 = (MODE == 1 && m0 + ra0 >= NOUT) ? make_float4(0.f, 0.f, 0.f, 0.f)    \
              : __ldg((const float4*)(A + (size_t)(m0 + ra0) * Ks + kk + sa0));    \
        fA1 = (MODE == 1 && m0 + ra1 >= NOUT) ? make_float4(0.f, 0.f, 0.f, 0.f)    \
              : __ldg((const float4*)(A + (size_t)(m0 + ra1) * Ks + kk + sa1));    \
        fB0 = __ldg((const float4*)(B + (size_t)(n0 + ra0) * Ks + kk + sa0));      \
        fB1 = __ldg((const float4*)(B + (size_t)(n0 + ra1) * Ks + kk + sa1));      \
    } while (0)

#define CVT_STS()                                                                  \
    do {                                                                           \
        ushort4 hv, lv;                                                            \
        split4(fA0, hv, lv);                                                       \
        *(ushort4*)(smAh + ra0 * ROWB + sa0 * 2) = hv;                             \
        *(ushort4*)(smAl + ra0 * ROWB + sa0 * 2) = lv;                             \
        split4(fA1, hv, lv);                                                       \
        *(ushort4*)(smAh + ra1 * ROWB + sa1 * 2) = hv;                             \
        *(ushort4*)(smAl + ra1 * ROWB + sa1 * 2) = lv;                             \
        split4(fB0, hv, lv);                                                       \
        *(ushort4*)(smBh + ra0 * ROWB + sa0 * 2) = hv;                             \
        *(ushort4*)(smBl + ra0 * ROWB + sa0 * 2) = lv;                             \
        split4(fB1, hv, lv);                                                       \
        *(ushort4*)(smBh + ra1 * ROWB + sa1 * 2) = hv;                             \
        *(ushort4*)(smBl + ra1 * ROWB + sa1 * 2) = lv;                             \
    } while (0)

    LDG_CHUNKS(0);

    int koff = 4 * t;                       // byte offset in 32B bf16 row
    for (int it = 0; it < kIters; it++) {
        __syncthreads();                    // previous compute done everywhere
        CVT_STS();
        __syncthreads();
        if (it + 1 < kIters) LDG_CHUNKS(it + 1);   // hidden under compute below

        uint32_t a[2][4];
        // ---- aH fragments (reused for Bh and Bl passes) ----
#pragma unroll
        for (int mi = 0; mi < 2; mi++) {
            const char* base = smAh + (wm + mi * 16 + g) * ROWB + koff;
            a[mi][0] = *(const uint32_t*)(base);
            a[mi][1] = *(const uint32_t*)(base + 8 * ROWB);
            a[mi][2] = *(const uint32_t*)(base + 16);
            a[mi][3] = *(const uint32_t*)(base + 8 * ROWB + 16);
        }
        // pass 0: aH x bH
#pragma unroll
        for (int nj = 0; nj < 4; nj++) {
            const char* bb = smBh + (wn + nj * 16 + g) * ROWB + koff;
            uint32_t b0 = *(const uint32_t*)(bb);
            uint32_t b1 = *(const uint32_t*)(bb + 16);
            uint32_t b2 = *(const uint32_t*)(bb + 8 * ROWB);
            uint32_t b3 = *(const uint32_t*)(bb + 8 * ROWB + 16);
#pragma unroll
            for (int mi = 0; mi < 2; mi++) {
                mma16816(acc[mi][nj * 2],     a[mi][0], a[mi][1], a[mi][2], a[mi][3], b0, b1);
                mma16816(acc[mi][nj * 2 + 1], a[mi][0], a[mi][1], a[mi][2], a[mi][3], b2, b3);
            }
        }
        // pass 1: aH x bL
#pragma unroll
        for (int nj = 0; nj < 4; nj++) {
            const char* bb = smBl + (wn + nj * 16 + g) * ROWB + koff;
            uint32_t b0 = *(const uint32_t*)(bb);
            uint32_t b1 = *(const uint32_t*)(bb + 16);
            uint32_t b2 = *(const uint32_t*)(bb + 8 * ROWB);
            uint32_t b3 = *(const uint32_t*)(bb + 8 * ROWB + 16);
#pragma unroll
            for (int mi = 0; mi < 2; mi++) {
                mma16816(acc[mi][nj * 2],     a[mi][0], a[mi][1], a[mi][2], a[mi][3], b0, b1);
                mma16816(acc[mi][nj * 2 + 1], a[mi][0], a[mi][1], a[mi][2], a[mi][3], b2, b3);
            }
        }
        // ---- aL fragments ----
#pragma unroll
        for (int mi = 0; mi < 2; mi++) {
            const char* base = smAl + (wm + mi * 16 + g) * ROWB + koff;
            a[mi][0] = *(const uint32_t*)(base);
            a[mi][1] = *(const uint32_t*)(base + 8 * ROWB);
            a[mi][2] = *(const uint32_t*)(base + 16);
            a[mi][3] = *(const uint32_t*)(base + 8 * ROWB + 16);
        }
        // pass 2: aL x bH
#pragma unroll
        for (int nj = 0; nj < 4; nj++) {
            const char* bb = smBh + (wn + nj * 16 + g) * ROWB + koff;
            uint32_t b0 = *(const uint32_t*)(bb);
            uint32_t b1 = *(const uint32_t*)(bb + 16);
            uint32_t b2 = *(const uint32_t*)(bb + 8 * ROWB);
            uint32_t b3 = *(const uint32_t*)(bb + 8 * ROWB + 16);
#pragma unroll
            for (int mi = 0; mi < 2; mi++) {
                mma16816(acc[mi][nj * 2],     a[mi][0], a[mi][1], a[mi][2], a[mi][3], b0, b1);
                mma16816(acc[mi][nj * 2 + 1], a[mi][0], a[mi][1], a[mi][2], a[mi][3], b2, b3);
            }
        }
    }
#undef LDG_CHUNKS
#undef CVT_STS

    // epilogue: c0,c1 at (m, n=2t), c2,c3 at (m+8, n=2t)
    int mrow = g;
    int ncol = t * 2;
#pragma unroll
    for (int mi = 0; mi < 2; mi++) {
        int m = m0 + wm + mi * 16 + mrow;
        if (MODE == 0) {
            float bv0 = bias[m], bv8 = bias[m + 8];
#pragma unroll
            for (int n8 = 0; n8 < 8; n8++) {
                int n = n0 + wn + n8 * 8 + ncol;
                float* c = acc[mi][n8];
                float2 lo = make_float2(fmaxf(c[0] + bv0, 0.f), fmaxf(c[1] + bv0, 0.f));
                float2 hi = make_float2(fmaxf(c[2] + bv8, 0.f), fmaxf(c[3] + bv8, 0.f));
                *(float2*)(out + (size_t)m * B_SZ + n) = lo;
                *(float2*)(out + (size_t)(m + 8) * B_SZ + n) = hi;
            }
        } else {
#pragma unroll
            for (int n8 = 0; n8 < 8; n8++) {
                int n = n0 + wn + n8 * 8 + ncol;
                float* c = acc[mi][n8];
                if (m < NOUT) {
                    atomicAdd(out + (size_t)n * NOUT + m, c[0]);
                    atomicAdd(out + (size_t)(n + 1) * NOUT + m, c[1]);
                }
                if (m + 8 < NOUT) {
                    atomicAdd(out + (size_t)n * NOUT + m + 8, c[2]);
                    atomicAdd(out + (size_t)(n + 1) * NOUT + m + 8, c[3]);
                }
            }
        }
    }
}

// ---------------------------------------------------------------------------
// Condensed layer: fp16 smem staging (R15-proven) + packed fp16w|u16idx
// metadata (one uint per f; 4 B/(o,f) vs 6 -> L2 traffic -33%).
// phase 0: fp32 [o][b] -> fp32 [o][b]
// phase 1: fp32 [o][b] -> fp32 [b][o] (g_a1t)
// ---------------------------------------------------------------------------
__global__ __launch_bounds__(1024) void cond_kernel(int phase, const float* __restrict__ bias) {
    extern __shared__ uint2 hsh[];   // [NMID], 4 halves each
    const float4* hin = (phase == 0) ? g_act0v : g_act1v;
    const uint4* pk = g_pk[phase];
    int bq = blockIdx.x;
    int b0 = bq * 4;
    int tid = threadIdx.x;

    for (int j = tid; j < NMID; j += 1024) {
        float4 v = hin[(size_t)j * (B_SZ / 4) + bq];
        __half2 p01 = __floats2half2_rn(v.x, v.y);
        __half2 p23 = __floats2half2_rn(v.z, v.w);
        uint2 u;
        u.x = *(uint32_t*)&p01;
        u.y = *(uint32_t*)&p23;
        hsh[j] = u;
    }
    __syncthreads();

#pragma unroll
    for (int oi = 0; oi < NMID / 1024; oi++) {
        int o = oi * 1024 + tid;
        float ax = 0.f, ay = 0.f, az = 0.f, aw = 0.f;
#pragma unroll
        for (int g = 0; g < FAN / 8; g++) {
            uint4 m0 = pk[(size_t)(2 * g) * NMID + o];
            uint4 m1 = pk[(size_t)(2 * g + 1) * NMID + o];
#define ACC(u)                                                              \
            {                                                               \
                uint2 p = hsh[(u) & 0xffff];                                \
                float wv = __half2float(__ushort_as_half(                   \
                               (unsigned short)((u) >> 16)));               \
                float2 f01 = __half22float2(*(__half2*)&p.x);               \
                float2 f23 = __half22float2(*(__half2*)&p.y);               \
                ax = fmaf(wv, f01.x, ax); ay = fmaf(wv, f01.y, ay);         \
                az = fmaf(wv, f23.x, az); aw = fmaf(wv, f23.y, aw);         \
            }
            ACC(m0.x) ACC(m0.y) ACC(m0.z) ACC(m0.w)
            ACC(m1.x) ACC(m1.y) ACC(m1.z) ACC(m1.w)
#undef ACC
        }
        float bv = bias[o];
        float4 r;
        r.x = fmaxf(ax + bv, 0.f); r.y = fmaxf(ay + bv, 0.f);
        r.z = fmaxf(az + bv, 0.f); r.w = fmaxf(aw + bv, 0.f);
        if (phase == 0) {
            g_act1v[(size_t)o * (B_SZ / 4) + bq] = r;
        } else {
            g_a1t[(size_t)(b0 + 0) * NMID + o] = r.x;
            g_a1t[(size_t)(b0 + 1) * NMID + o] = r.y;
            g_a1t[(size_t)(b0 + 2) * NMID + o] = r.z;
            g_a1t[(size_t)(b0 + 3) * NMID + o] = r.w;
        }
    }
}

// ---------------------------------------------------------------------------
__global__ void init_out_kernel(const float* __restrict__ bout, float* __restrict__ out) {
    int t = blockIdx.x * blockDim.x + threadIdx.x;
    if (t < B_SZ * NOUT) out[t] = bout[t % NOUT];
}

// ---------------------------------------------------------------------------
extern "C" void kernel_launch(void* const* d_in, const int* in_sizes, int n_in,
                              void* d_out, int out_size) {
    const float* x    = (const float*)d_in[0];
    const float* Win  = (const float*)d_in[1];
    const float* bin  = (const float*)d_in[2];
    const float* Wmid = (const float*)d_in[3];
    const float* bmid = (const float*)d_in[4];
    const float* Wout = (const float*)d_in[5];
    const float* bout = (const float*)d_in[6];
    const int*   idx  = (const int*)d_in[7];    // int32 (JAX x64 disabled)
    float* out = (float*)d_out;

    cudaFuncSetAttribute(cond_kernel, cudaFuncAttributeMaxDynamicSharedMemorySize, 65536);

    // cond prep (scratch globals bound inside device code)
    prep_pk_kernel<<<(NCOND * (FAN / 4) * NMID + 255) / 256, 256>>>(Wmid, idx);

    // GEMM1: relu(W_in x^T + b_in) -> g_act0 fp32 [o][b]; fp32 staged, split in-kernel
    mma_gemm<0><<<dim3(B_SZ / TBN, NMID / TBM, 1), GEMM_THREADS>>>(
        Win, x, bin, nullptr, NIN / TBK);

    // condensed layers (4 batch cols per CTA, 128 CTAs, fp16 smem staging)
    cond_kernel<<<B_SZ / 4, 1024, 65536>>>(0, bmid);
    cond_kernel<<<B_SZ / 4, 1024, 65536>>>(1, bmid + NMID);

    // GEMM3: out[b][m] = act1 . W_out^T + b_out  (split-K=8, atomic)
    init_out_kernel<<<(B_SZ * NOUT + 255) / 256, 256>>>(bout, out);
    mma_gemm<1><<<dim3(B_SZ / TBN, MPAD / TBM, 8), GEMM_THREADS>>>(
        Wout, nullptr, nullptr, out, NMID / (TBK * 8));
}